// round 9
// baseline (speedup 1.0000x reference)
#include <cuda_runtime.h>
#include <cstdint>

// Problem constants
#define B_   16
#define N_   2048
#define D_   128
#define Q_   8
#define K_   1024
#define TOK  (B_ * N_)          // 32768 tokens

// Tiling
#define BM   64                 // tokens per CTA
#define BN   128                // codes per K-chunk
#define NBLK (TOK / BM)         // 512 CTAs
#define NCHUNK (K_ / BN)        // 8 chunks
#define ASTR 68                 // padded smem stride for A^T (64 + 4)

// SMEM layout: sBt (swizzled, 64KB) | sAt | sIdx | sRed
#define SBT_BYTES (D_ * BN * 4)                 // 65536, row = 512B, no pad
#define SAT_OFF   SBT_BYTES
#define SAT_BYTES (D_ * ASTR * 4)               // 34816
#define SIDX_OFF  (SAT_OFF + SAT_BYTES)
#define SRED_OFF  (SIDX_OFF + BM * 4)
#define SMEM_BYTES (SRED_OFF + 64)

// Scratch (allocation-free rule: __device__ globals)
__device__ float g_c2[Q_ * K_];              // 32 KB
__device__ float g_commit[Q_ * NBLK];        // 16 KB

// ---- packed f32x2 helpers -------------------------------------------------
__device__ __forceinline__ void ffma2(unsigned long long& acc,
                                      unsigned long long a2,
                                      unsigned long long b2) {
    asm("fma.rn.f32x2 %0, %1, %2, %0;" : "+l"(acc) : "l"(a2), "l"(b2));
}
__device__ __forceinline__ unsigned long long mul2(unsigned long long a,
                                                   unsigned long long b) {
    unsigned long long r;
    asm("mul.rn.f32x2 %0, %1, %2;" : "=l"(r) : "l"(a), "l"(b));
    return r;
}
__device__ __forceinline__ unsigned long long dup2(float x) {
    unsigned long long r;
    asm("mov.b64 %0, {%1, %1};" : "=l"(r) : "f"(x));
    return r;
}
__device__ __forceinline__ void unpack2(unsigned long long p, float& lo, float& hi) {
    asm("mov.b64 {%0, %1}, %2;" : "=f"(lo), "=f"(hi) : "l"(p));
}
__device__ __forceinline__ float f4get(const float4& v, int j) {
    switch (j) { case 0: return v.x; case 1: return v.y;
                 case 2: return v.z; default: return v.w; }
}

// ---------------------------------------------------------------------------
// c2[q][k] = sum_d codebook[q][k][d]^2
// ---------------------------------------------------------------------------
__global__ void c2_kernel(const float* __restrict__ cb) {
    int code = blockIdx.x * blockDim.x + threadIdx.x;
    if (code >= Q_ * K_) return;
    const float4* p = reinterpret_cast<const float4*>(cb + (size_t)code * D_);
    float s = 0.f;
#pragma unroll
    for (int i = 0; i < D_ / 4; i++) {
        float4 v = p[i];
        s += v.x * v.x + v.y * v.y + v.z * v.z + v.w * v.w;
    }
    g_c2[code] = s;
}

// ---------------------------------------------------------------------------
// Fused RVQ, all 8 stages. Residual tile resident in SMEM.
//
// sBt layout (XOR-swizzled, conflict-free both directions):
//   element (d, k) at byte  d*512 + (((k>>2) ^ (d>>2)) << 4) + (k&3)*4
//   - stores: STS.128 per row, lanes span d>>2 -> distinct 16B bank groups
//   - mainloop reads: LDS.64 pairs {2tx+32p, +1}, chunk permutation per d
//
// Argmin via argmax of acc = dot - c2/2 (acc initialized to -c2/2; exact
// monotone map of dist = c2 - 2*dot; strict-> ascending-k keeps first-min).
// ---------------------------------------------------------------------------
__global__ void __launch_bounds__(256, 2)
rvq_fused_kernel(const float* __restrict__ x,
                 const float* __restrict__ cb_all,   // [Q][K][D]
                 float* __restrict__ out)            // [TOK*Q | TOK*D | Q]
{
    extern __shared__ char smem[];
    char*  sBt  = smem;                                    // 64 KB swizzled
    float* sAt  = reinterpret_cast<float*>(smem + SAT_OFF);
    int*   sIdx = reinterpret_cast<int*>(smem + SIDX_OFF);
    float* sRed = reinterpret_cast<float*>(smem + SRED_OFF);

    const int tid = threadIdx.x;
    const int tx = tid & 15;        // code group 0..15
    const int ty = tid >> 4;        // token group 0..15
    const int token0 = blockIdx.x * BM;

    // mainloop B byte offsets within a row, before per-d XOR:
    //   ccp16h[p] = (((tx>>1) + 8p) << 4) + (tx&1)*8   (bit3 disjoint from XOR)
    unsigned ccp16h[4];
#pragma unroll
    for (int p = 0; p < 4; p++)
        ccp16h[p] = ((unsigned)((tx >> 1) + 8 * p) << 4) + (unsigned)(tx & 1) * 8u;

    // ---- load x tile transposed: sAt[d][t] (one-time) ----
    for (int i = tid; i < BM * (D_ / 4); i += 256) {
        int t = i >> 5, c4 = i & 31;
        float4 v = *reinterpret_cast<const float4*>(
            x + (size_t)(token0 + t) * D_ + c4 * 4);
        sAt[(c4 * 4 + 0) * ASTR + t] = v.x;
        sAt[(c4 * 4 + 1) * ASTR + t] = v.y;
        sAt[(c4 * 4 + 2) * ASTR + t] = v.z;
        sAt[(c4 * 4 + 3) * ASTR + t] = v.w;
    }
    __syncthreads();

    const int c4 = tid & 31;        // store-path row-quad (d>>2)
    const int kg = tid >> 5;        // store-path k-group 0..7
    const unsigned long long negHalf = dup2(-0.5f);

    for (int stage = 0; stage < Q_; stage++) {
        const float* cb = cb_all + (size_t)stage * K_ * D_;
        const float* c2 = g_c2 + stage * K_;

        float bestA[4];             // running max of (dot - c2/2)
        int   bestI[4];
#pragma unroll
        for (int i = 0; i < 4; i++) { bestA[i] = -3.4e38f; bestI[i] = 0; }

        for (int chunk = 0; chunk < NCHUNK; chunk++) {
            const int kbase = chunk * BN;

            // ---- swizzled transpose-store of the code chunk ----
            // Phase 1: batch ALL 16 gmem loads first (guaranteed MLP=16;
            // one L2-latency exposure per chunk instead of up to four).
            float4 v[4][4];                       // [ph][kk]
#pragma unroll
            for (int ph = 0; ph < 4; ph++) {
                const int k0 = kg * 16 + ph * 4;
#pragma unroll
                for (int kk = 0; kk < 4; kk++)
                    v[ph][kk] = *reinterpret_cast<const float4*>(
                        cb + (size_t)(kbase + k0 + kk) * D_ + c4 * 4);
            }
            // Phase 2: register transpose + swizzled STS.128
            // thread: rows 4*c4..4*c4+3, k = kg*16 + ph*4 + {0..3}
#pragma unroll
            for (int ph = 0; ph < 4; ph++) {
                const int k0 = kg * 16 + ph * 4;
                const unsigned ccsw = ((unsigned)(k0 >> 2) ^ (unsigned)c4) << 4;
#pragma unroll
                for (int j = 0; j < 4; j++) {
                    float4 w = make_float4(f4get(v[ph][0], j), f4get(v[ph][1], j),
                                           f4get(v[ph][2], j), f4get(v[ph][3], j));
                    *reinterpret_cast<float4*>(
                        sBt + (unsigned)(4 * c4 + j) * 512u + ccsw) = w;
                }
            }
            __syncthreads();

            // ---- acc init = -c2/2 (packed pair, same for all 4 tokens) ----
            unsigned long long acc[4][4];
#pragma unroll
            for (int p = 0; p < 4; p++) {
                const unsigned long long c2pair =
                    *reinterpret_cast<const unsigned long long*>(
                        c2 + kbase + tx * 2 + 32 * p);
                const unsigned long long init = mul2(c2pair, negHalf);
#pragma unroll
                for (int i = 0; i < 4; i++) acc[i][p] = init;
            }

            // ---- 4x8 register-tile GEMM over d, packed f32x2 (FFMA2) ----
            // acc[i][p]: token ty*4+i, codes kbase + tx*2 + 32*p + {0,1}
#pragma unroll 4
            for (int d = 0; d < D_; d++) {
                float4 a = *reinterpret_cast<const float4*>(sAt + d * ASTR + ty * 4);
                const char* rowb = sBt + (unsigned)d * 512u;
                const unsigned e = ((unsigned)(d >> 2)) << 4;   // hoisted per 4-d
                unsigned long long b2[4];
#pragma unroll
                for (int p = 0; p < 4; p++)
                    b2[p] = *reinterpret_cast<const unsigned long long*>(
                        rowb + (ccp16h[p] ^ e));
                unsigned long long a2[4];
                a2[0] = dup2(a.x); a2[1] = dup2(a.y);
                a2[2] = dup2(a.z); a2[3] = dup2(a.w);
#pragma unroll
                for (int i = 0; i < 4; i++)
#pragma unroll
                    for (int p = 0; p < 4; p++)
                        ffma2(acc[i][p], a2[i], b2[p]);
            }

            // ---- epilogue: running argmax of acc, ascending k, strict > ----
#pragma unroll
            for (int p = 0; p < 4; p++) {
                int k0 = kbase + tx * 2 + 32 * p;
#pragma unroll
                for (int i = 0; i < 4; i++) {
                    float alo, ahi;
                    unpack2(acc[i][p], alo, ahi);
                    if (alo > bestA[i]) { bestA[i] = alo; bestI[i] = k0; }
                    if (ahi > bestA[i]) { bestA[i] = ahi; bestI[i] = k0 + 1; }
                }
            }
            __syncthreads();   // before sBt is overwritten next chunk
        }

        // ---- cross-lane argmax over the 16 tx lanes (offsets < 16) ----
#pragma unroll
        for (int i = 0; i < 4; i++) {
            float ba = bestA[i];
            int   bi = bestI[i];
#pragma unroll
            for (int off = 8; off; off >>= 1) {
                float oa = __shfl_xor_sync(0xffffffffu, ba, off);
                int   oi = __shfl_xor_sync(0xffffffffu, bi, off);
                if (oa > ba || (oa == ba && oi < bi)) { ba = oa; bi = oi; }
            }
            if (tx == 0) {
                int t = ty * 4 + i;
                sIdx[t] = bi;
                out[(size_t)(token0 + t) * Q_ + stage] = (float)bi;
            }
        }
        __syncthreads();

        // ---- in-place residual update + commit partial (conflict-free) ----
        float lsq = 0.f;
        for (int i = tid; i < BM * (D_ / 4); i += 256) {
            int t = i & 63, c = i >> 6;       // c in 0..31, lanes span t
            int k = sIdx[t];
            float4 cv = *reinterpret_cast<const float4*>(cb + (size_t)k * D_ + c * 4);
            float* r0p = sAt + (c * 4 + 0) * ASTR + t;
            float* r1p = sAt + (c * 4 + 1) * ASTR + t;
            float* r2p = sAt + (c * 4 + 2) * ASTR + t;
            float* r3p = sAt + (c * 4 + 3) * ASTR + t;
            float r0 = *r0p - cv.x;
            float r1 = *r1p - cv.y;
            float r2 = *r2p - cv.z;
            float r3 = *r3p - cv.w;
            *r0p = r0; *r1p = r1; *r2p = r2; *r3p = r3;
            lsq += r0 * r0 + r1 * r1 + r2 * r2 + r3 * r3;
        }
#pragma unroll
        for (int off = 16; off; off >>= 1)
            lsq += __shfl_xor_sync(0xffffffffu, lsq, off);
        if ((tid & 31) == 0) sRed[tid >> 5] = lsq;
        __syncthreads();   // orders sAt updates before next stage's reads
        if (tid == 0) {
            float s = 0.f;
#pragma unroll
            for (int w = 0; w < 8; w++) s += sRed[w];   // fixed order
            g_commit[stage * NBLK + blockIdx.x] = s;
        }
    }

    // ---- quantized = x - residual_final ----
    float* quant = out + (size_t)TOK * Q_;
    for (int i = tid; i < BM * (D_ / 4); i += 256) {
        int t = i >> 5, cc = i & 31;
        float4 xv = *reinterpret_cast<const float4*>(
            x + (size_t)(token0 + t) * D_ + cc * 4);
        float4 qv;
        qv.x = xv.x - sAt[(cc * 4 + 0) * ASTR + t];
        qv.y = xv.y - sAt[(cc * 4 + 1) * ASTR + t];
        qv.z = xv.z - sAt[(cc * 4 + 2) * ASTR + t];
        qv.w = xv.w - sAt[(cc * 4 + 3) * ASTR + t];
        *reinterpret_cast<float4*>(quant + (size_t)(token0 + t) * D_ + cc * 4) = qv;
    }
}

// ---------------------------------------------------------------------------
// commits[q] = sum(partials) / (TOK*D)   — warp-per-q, deterministic tree
// ---------------------------------------------------------------------------
__global__ void commit_kernel(float* __restrict__ out)
{
    int w = threadIdx.x >> 5;      // q = warp id, 8 warps
    int l = threadIdx.x & 31;
    if (w >= Q_) return;
    double s = 0.0;
#pragma unroll
    for (int j = 0; j < NBLK / 32; j++)                 // fixed order per lane
        s += (double)g_commit[w * NBLK + j * 32 + l];
#pragma unroll
    for (int off = 16; off; off >>= 1)                  // fixed tree: determ.
        s += __shfl_xor_sync(0xffffffffu, s, off);
    if (l == 0)
        out[(size_t)TOK * Q_ + (size_t)TOK * D_ + w] =
            (float)(s / ((double)TOK * (double)D_));
}

// ---------------------------------------------------------------------------
extern "C" void kernel_launch(void* const* d_in, const int* in_sizes, int n_in,
                              void* d_out, int out_size)
{
    const float* x  = (const float*)d_in[0];   // [B,N,D]
    const float* cb = (const float*)d_in[1];   // [Q,K,D]
    float* out = (float*)d_out;                // [TOK*Q | TOK*D | Q]

    cudaFuncSetAttribute(rvq_fused_kernel,
                         cudaFuncAttributeMaxDynamicSharedMemorySize, SMEM_BYTES);

    c2_kernel<<<(Q_ * K_ + 127) / 128, 128>>>(cb);
    rvq_fused_kernel<<<NBLK, 256, SMEM_BYTES>>>(x, cb, out);
    commit_kernel<<<1, 256>>>(out);
}

// round 16
// speedup vs baseline: 1.1084x; 1.1084x over previous
#include <cuda_runtime.h>
#include <cstdint>
#include <cfloat>

// Problem constants
#define B_   16
#define N_   2048
#define D_   128
#define Q_   8
#define K_   1024
#define TOK  (B_ * N_)          // 32768 tokens

// Tiling
#define BM   64                 // tokens per CTA
#define BN   64                 // codes per chunk
#define NCH  (K_ / BN)          // 16 chunks
#define NBLK (TOK / BM)         // 512 CTAs
#define ASTR 72                 // sAt stride: (k*72+m) -> banks tg*8+g distinct
#define BSTR 132                // B planes [n][k] stride: banks 4g+tg distinct

// SMEM layout (floats): sBh | sBl | sAt | sTop | sIdx | sRed
#define SBH_F    (BN * BSTR)                  // 8448
#define SAT_OFF  (2 * SBH_F)                  // 16896
#define SAT_F    (D_ * ASTR)                  // 9216
#define STOP_OFF (SAT_OFF + SAT_F)            // 26112
#define STOP_F   (BM * 8)                     // 64 tokens x 2 warpcols x 4
#define SIDX_OFF (STOP_OFF + STOP_F)
#define SRED_OFF (SIDX_OFF + BM)
#define SMEM_F   (SRED_OFF + 16)
#define SMEM_BYTES (SMEM_F * 4)               // ~104.4 KB -> occupancy 2

// Scratch (allocation-free rule: __device__ globals)
__device__ float g_c2[Q_ * K_];
__device__ float g_commit[Q_ * NBLK];

// ---- helpers --------------------------------------------------------------
__device__ __forceinline__ unsigned tf32cvt(float x) {
    unsigned r;
    asm("cvt.rna.tf32.f32 %0, %1;" : "=r"(r) : "f"(x));
    return r;
}
__device__ __forceinline__ void mma1688(float* c, const unsigned* a,
                                        unsigned b0, unsigned b1) {
    asm volatile(
        "mma.sync.aligned.m16n8k8.row.col.f32.tf32.tf32.f32 "
        "{%0,%1,%2,%3}, {%4,%5,%6,%7}, {%8,%9}, {%0,%1,%2,%3};"
        : "+f"(c[0]), "+f"(c[1]), "+f"(c[2]), "+f"(c[3])
        : "r"(a[0]), "r"(a[1]), "r"(a[2]), "r"(a[3]), "r"(b0), "r"(b1));
}
// maximize score; ties -> smaller index (first-min semantics)
__device__ __forceinline__ bool better(float a, int ia, float b, int ib) {
    return (a > b) || (a == b && ia < ib);
}
__device__ __forceinline__ void top2upd(float s, int idx,
                                        float& s1, int& i1, float& s2, int& i2) {
    if (better(s, idx, s1, i1)) { s2 = s1; i2 = i1; s1 = s; i1 = idx; }
    else if (better(s, idx, s2, i2)) { s2 = s; i2 = idx; }
}
__device__ __forceinline__ void top2merge(float& s1, int& i1, float& s2, int& i2,
                                          float os1, int oi1, float os2, int oi2) {
    if (better(os1, oi1, s1, i1)) {
        float ns2; int ni2;
        if (better(s1, i1, os2, oi2)) { ns2 = s1; ni2 = i1; }
        else                          { ns2 = os2; ni2 = oi2; }
        s1 = os1; i1 = oi1; s2 = ns2; i2 = ni2;
    } else {
        if (better(os1, oi1, s2, i2)) { s2 = os1; i2 = oi1; }
    }
}

// ---------------------------------------------------------------------------
// c2[q][k] = sum_d codebook[q][k][d]^2
// ---------------------------------------------------------------------------
__global__ void c2_kernel(const float* __restrict__ cb) {
    int code = blockIdx.x * blockDim.x + threadIdx.x;
    if (code >= Q_ * K_) return;
    const float4* p = reinterpret_cast<const float4*>(cb + (size_t)code * D_);
    float s = 0.f;
#pragma unroll
    for (int i = 0; i < D_ / 4; i++) {
        float4 v = p[i];
        s += v.x * v.x + v.y * v.y + v.z * v.z + v.w * v.w;
    }
    g_c2[code] = s;
}

// ---------------------------------------------------------------------------
// Fused RVQ, all 8 stages: 3xTF32 mma.sync scores -> per-token top-2 ->
// exact fp32 rescore (preserves fp32 argmin semantics) -> residual update.
// score = dot - c2/2 (maximize)  ==  argmin(c2 - 2*dot) exactly.
// ---------------------------------------------------------------------------
__global__ void __launch_bounds__(256, 2)
rvq_mma_kernel(const float* __restrict__ x,
               const float* __restrict__ cb_all,   // [Q][K][D]
               float* __restrict__ out)            // [TOK*Q | TOK*D | Q]
{
    extern __shared__ float smem[];
    float* sBh  = smem;                 // tf32-hi plane [n][k], stride BSTR
    float* sBl  = smem + SBH_F;         // tf32-lo plane
    float* sAt  = smem + SAT_OFF;       // residual^T [d][ASTR]
    float* sTop = smem + STOP_OFF;      // [token][warpcol][4]
    int*   sIdx = reinterpret_cast<int*>(smem + SIDX_OFF);
    float* sRed = smem + SRED_OFF;

    const int tid  = threadIdx.x;
    const int lane = tid & 31;
    const int warp = tid >> 5;
    const int wm = warp & 3;            // m-tile: tokens wm*16..+15
    const int wn = warp >> 2;           // n-half: codes wn*32..+31 per chunk
    const int g  = lane >> 2;           // groupID
    const int tg = lane & 3;            // threadID_in_group
    const int m0 = wm * 16;
    const int token0 = blockIdx.x * BM;

    // ---- load x tile transposed: sAt[d][t] (one-time) ----
    for (int i = tid; i < BM * (D_ / 4); i += 256) {
        int t = i >> 5, c4 = i & 31;
        float4 v = *reinterpret_cast<const float4*>(
            x + (size_t)(token0 + t) * D_ + c4 * 4);
        sAt[(c4 * 4 + 0) * ASTR + t] = v.x;
        sAt[(c4 * 4 + 1) * ASTR + t] = v.y;
        sAt[(c4 * 4 + 2) * ASTR + t] = v.z;
        sAt[(c4 * 4 + 3) * ASTR + t] = v.w;
    }
    __syncthreads();

    for (int stage = 0; stage < Q_; stage++) {
        const float* cb = cb_all + (size_t)stage * K_ * D_;
        const float* c2 = g_c2 + stage * K_;

        // per-thread top-2 per row (rows: m0+g and m0+g+8)
        float s1[2] = {-FLT_MAX, -FLT_MAX}, s2[2] = {-FLT_MAX, -FLT_MAX};
        int   i1[2] = {0x7fffffff, 0x7fffffff}, i2[2] = {0x7fffffff, 0x7fffffff};

        for (int chunk = 0; chunk < NCH; chunk++) {
            const int kbase = chunk * BN;

            // ---- load + tf32-split codes into sBh/sBl [n][k] ----
            {
                const int n   = tid >> 2;
                const int ks0 = (tid & 3) * 32;
                const float4* src = reinterpret_cast<const float4*>(
                    cb + (size_t)(kbase + n) * D_ + ks0);
                uint4* dh = reinterpret_cast<uint4*>(sBh + n * BSTR + ks0);
                uint4* dl = reinterpret_cast<uint4*>(sBl + n * BSTR + ks0);
#pragma unroll
                for (int i = 0; i < 8; i++) {
                    float4 v = src[i];
                    uint4 h, l;
                    h.x = tf32cvt(v.x); l.x = tf32cvt(v.x - __uint_as_float(h.x));
                    h.y = tf32cvt(v.y); l.y = tf32cvt(v.y - __uint_as_float(h.y));
                    h.z = tf32cvt(v.z); l.z = tf32cvt(v.z - __uint_as_float(h.z));
                    h.w = tf32cvt(v.w); l.w = tf32cvt(v.w - __uint_as_float(h.w));
                    dh[i] = h; dl[i] = l;
                }
            }
            __syncthreads();

            // ---- acc init = -c2/2 at the c-fragment positions ----
            float acc[4][4];
#pragma unroll
            for (int nt = 0; nt < 4; nt++) {
                int c0 = kbase + wn * 32 + nt * 8 + 2 * tg;
                float h0 = -0.5f * __ldg(c2 + c0);
                float h1 = -0.5f * __ldg(c2 + c0 + 1);
                acc[nt][0] = h0; acc[nt][1] = h1;   // row g
                acc[nt][2] = h0; acc[nt][3] = h1;   // row g+8
            }

            // ---- 3xTF32 mma mainloop over k ----
#pragma unroll 4
            for (int ks = 0; ks < D_ / 8; ks++) {
                const int k0 = ks * 8;
                const float* ap = sAt + (k0 + tg) * ASTR + m0 + g;
                float a00 = ap[0];              // (row g,   col tg)
                float a10 = ap[8];              // (row g+8, col tg)
                float a01 = ap[4 * ASTR];       // (row g,   col tg+4)
                float a11 = ap[4 * ASTR + 8];   // (row g+8, col tg+4)
                unsigned ah[4], al[4];
                ah[0] = tf32cvt(a00); al[0] = tf32cvt(a00 - __uint_as_float(ah[0]));
                ah[1] = tf32cvt(a10); al[1] = tf32cvt(a10 - __uint_as_float(ah[1]));
                ah[2] = tf32cvt(a01); al[2] = tf32cvt(a01 - __uint_as_float(ah[2]));
                ah[3] = tf32cvt(a11); al[3] = tf32cvt(a11 - __uint_as_float(ah[3]));
#pragma unroll
                for (int nt = 0; nt < 4; nt++) {
                    const int bro = (wn * 32 + nt * 8 + g) * BSTR + k0 + tg;
                    unsigned bh0 = __float_as_uint(sBh[bro]);
                    unsigned bh1 = __float_as_uint(sBh[bro + 4]);
                    unsigned bl0 = __float_as_uint(sBl[bro]);
                    unsigned bl1 = __float_as_uint(sBl[bro + 4]);
                    mma1688(acc[nt], ah, bh0, bh1);   // hi*hi
                    mma1688(acc[nt], ah, bl0, bl1);   // hi*lo
                    mma1688(acc[nt], al, bh0, bh1);   // lo*hi
                }
            }

            // ---- top-2 update (ascending code index within thread) ----
#pragma unroll
            for (int nt = 0; nt < 4; nt++) {
                int c0 = kbase + wn * 32 + nt * 8 + 2 * tg;
                top2upd(acc[nt][0], c0,     s1[0], i1[0], s2[0], i2[0]);
                top2upd(acc[nt][1], c0 + 1, s1[0], i1[0], s2[0], i2[0]);
                top2upd(acc[nt][2], c0,     s1[1], i1[1], s2[1], i2[1]);
                top2upd(acc[nt][3], c0 + 1, s1[1], i1[1], s2[1], i2[1]);
            }
            __syncthreads();   // before sBh/sBl overwrite
        }

        // ---- merge across the 4 lanes of each row group ----
#pragma unroll
        for (int off = 1; off <= 2; off <<= 1) {
#pragma unroll
            for (int r = 0; r < 2; r++) {
                float os1 = __shfl_xor_sync(0xffffffffu, s1[r], off);
                int   oi1 = __shfl_xor_sync(0xffffffffu, i1[r], off);
                float os2 = __shfl_xor_sync(0xffffffffu, s2[r], off);
                int   oi2 = __shfl_xor_sync(0xffffffffu, i2[r], off);
                top2merge(s1[r], i1[r], s2[r], i2[r], os1, oi1, os2, oi2);
            }
        }
        if (tg == 0) {
#pragma unroll
            for (int r = 0; r < 2; r++) {
                int t = m0 + g + r * 8;
                float* dst = sTop + (t * 2 + wn) * 4;
                dst[0] = s1[r]; dst[1] = __int_as_float(i1[r]);
                dst[2] = s2[r]; dst[3] = __int_as_float(i2[r]);
            }
        }
        __syncthreads();

        // ---- exact fp32 rescore of top-2, pick winner ----
        if (tid < 2 * BM) {
            const int t = tid >> 1, cnd = tid & 1;
            const float* e0 = sTop + t * 8;
            float a1s = e0[0]; int a1i = __float_as_int(e0[1]);
            float a2s = e0[2]; int a2i = __float_as_int(e0[3]);
            float b1s = e0[4]; int b1i = __float_as_int(e0[5]);
            float b2s = e0[6]; int b2i = __float_as_int(e0[7]);
            top2merge(a1s, a1i, a2s, a2i, b1s, b1i, b2s, b2i);
            const int k = cnd ? a2i : a1i;
            const float4* crow = reinterpret_cast<const float4*>(cb + (size_t)k * D_);
            float p0 = 0.f, p1 = 0.f, p2 = 0.f, p3 = 0.f;
#pragma unroll
            for (int j = 0; j < 32; j++) {
                float4 cv = crow[j];
                p0 = fmaf(cv.x, sAt[(j * 4 + 0) * ASTR + t], p0);
                p1 = fmaf(cv.y, sAt[(j * 4 + 1) * ASTR + t], p1);
                p2 = fmaf(cv.z, sAt[(j * 4 + 2) * ASTR + t], p2);
                p3 = fmaf(cv.w, sAt[(j * 4 + 3) * ASTR + t], p3);
            }
            float sc = (p0 + p1) + (p2 + p3) - 0.5f * __ldg(c2 + k);
            float osc = __shfl_xor_sync(0xffffffffu, sc, 1);
            int   okk = __shfl_xor_sync(0xffffffffu, k, 1);
            if (cnd == 0) {
                int win = better(sc, k, osc, okk) ? k : okk;
                sIdx[t] = win;
                out[(size_t)(token0 + t) * Q_ + stage] = (float)win;
            }
        }
        __syncthreads();

        // ---- in-place residual update + commit partial ----
        float lsq = 0.f;
        for (int i = tid; i < BM * (D_ / 4); i += 256) {
            int t = i & 63, c = i >> 6;
            int k = sIdx[t];
            float4 cv = *reinterpret_cast<const float4*>(cb + (size_t)k * D_ + c * 4);
            float* r0p = sAt + (c * 4 + 0) * ASTR + t;
            float* r1p = sAt + (c * 4 + 1) * ASTR + t;
            float* r2p = sAt + (c * 4 + 2) * ASTR + t;
            float* r3p = sAt + (c * 4 + 3) * ASTR + t;
            float r0 = *r0p - cv.x;
            float r1 = *r1p - cv.y;
            float r2 = *r2p - cv.z;
            float r3 = *r3p - cv.w;
            *r0p = r0; *r1p = r1; *r2p = r2; *r3p = r3;
            lsq += r0 * r0 + r1 * r1 + r2 * r2 + r3 * r3;
        }
#pragma unroll
        for (int off = 16; off; off >>= 1)
            lsq += __shfl_xor_sync(0xffffffffu, lsq, off);
        if ((tid & 31) == 0) sRed[tid >> 5] = lsq;
        __syncthreads();
        if (tid == 0) {
            float s = 0.f;
#pragma unroll
            for (int w = 0; w < 8; w++) s += sRed[w];   // fixed order
            g_commit[stage * NBLK + blockIdx.x] = s;
        }
    }

    // ---- quantized = x - residual_final ----
    float* quant = out + (size_t)TOK * Q_;
    for (int i = tid; i < BM * (D_ / 4); i += 256) {
        int t = i >> 5, cc = i & 31;
        float4 xv = *reinterpret_cast<const float4*>(
            x + (size_t)(token0 + t) * D_ + cc * 4);
        float4 qv;
        qv.x = xv.x - sAt[(cc * 4 + 0) * ASTR + t];
        qv.y = xv.y - sAt[(cc * 4 + 1) * ASTR + t];
        qv.z = xv.z - sAt[(cc * 4 + 2) * ASTR + t];
        qv.w = xv.w - sAt[(cc * 4 + 3) * ASTR + t];
        *reinterpret_cast<float4*>(quant + (size_t)(token0 + t) * D_ + cc * 4) = qv;
    }
}

// ---------------------------------------------------------------------------
// commits[q] = sum(partials) / (TOK*D)   — warp-per-q, deterministic tree
// ---------------------------------------------------------------------------
__global__ void commit_kernel(float* __restrict__ out)
{
    int w = threadIdx.x >> 5;
    int l = threadIdx.x & 31;
    if (w >= Q_) return;
    double s = 0.0;
#pragma unroll
    for (int j = 0; j < NBLK / 32; j++)
        s += (double)g_commit[w * NBLK + j * 32 + l];
#pragma unroll
    for (int off = 16; off; off >>= 1)
        s += __shfl_xor_sync(0xffffffffu, s, off);
    if (l == 0)
        out[(size_t)TOK * Q_ + (size_t)TOK * D_ + w] =
            (float)(s / ((double)TOK * (double)D_));
}

// ---------------------------------------------------------------------------
extern "C" void kernel_launch(void* const* d_in, const int* in_sizes, int n_in,
                              void* d_out, int out_size)
{
    const float* x  = (const float*)d_in[0];   // [B,N,D]
    const float* cb = (const float*)d_in[1];   // [Q,K,D]
    float* out = (float*)d_out;                // [TOK*Q | TOK*D | Q]

    cudaFuncSetAttribute(rvq_mma_kernel,
                         cudaFuncAttributeMaxDynamicSharedMemorySize, SMEM_BYTES);

    c2_kernel<<<(Q_ * K_ + 127) / 128, 128>>>(cb);
    rvq_mma_kernel<<<NBLK, 256, SMEM_BYTES>>>(x, cb, out);
    commit_kernel<<<1, 256>>>(out);
}